// round 15
// baseline (speedup 1.0000x reference)
#include <cuda_runtime.h>
#include <cuda_fp16.h>
#include <math.h>
#include <stdint.h>

#define BB 2
#define SS 2048
#define HID 1024
#define HEADS 16
#define DHEAD 64
#define INNER 1024
#define BH (BB*HEADS)

// Scratch (fp16). q,k in [B,H,S,D]; v TRANSPOSED [B,H,D,S]; att [B,S,INNER].
__device__ __half g_q[BB*HEADS*SS*DHEAD];
__device__ __half g_k[BB*HEADS*SS*DHEAD];
__device__ __half g_v[BB*HEADS*SS*DHEAD];
__device__ __half g_att[BB*SS*INNER];
__device__ __half g_rw[4*HID*INNER];   // Wq,Wk,Wv,Wo TRANSPOSED [n][k] fp16
__device__ __half g_rx[3*BB*SS*HID];   // query,key,value fp16

#define LOG2E 1.4426950408889634f

__device__ __forceinline__ __half hrn(float x) { return __float2half_rn(x); }

__device__ __forceinline__ uint32_t pack2(float a, float b) {
    __half2 h = __halves2half2(hrn(a), hrn(b));
    uint32_t u;
    *(__half2*)&u = h;
    return u;
}

__device__ __forceinline__ void mma16(float* c, const uint32_t* a, const uint32_t* b) {
    asm volatile(
        "mma.sync.aligned.m16n8k16.row.col.f32.f16.f16.f32 "
        "{%0,%1,%2,%3}, {%4,%5,%6,%7}, {%8,%9}, {%0,%1,%2,%3};"
        : "+f"(c[0]), "+f"(c[1]), "+f"(c[2]), "+f"(c[3])
        : "r"(a[0]), "r"(a[1]), "r"(a[2]), "r"(a[3]), "r"(b[0]), "r"(b[1]));
}

__device__ __forceinline__ void ldm4(uint32_t& r0, uint32_t& r1, uint32_t& r2,
                                     uint32_t& r3, uint32_t addr) {
    asm volatile(
        "ldmatrix.sync.aligned.m8n8.x4.shared.b16 {%0,%1,%2,%3}, [%4];"
        : "=r"(r0), "=r"(r1), "=r"(r2), "=r"(r3) : "r"(addr));
}

__device__ __forceinline__ uint32_t smaddr(const void* p) {
    return (uint32_t)__cvta_generic_to_shared(p);
}
__device__ __forceinline__ void cp16(uint32_t dst, const void* src) {
    asm volatile("cp.async.cg.shared.global [%0], [%1], 16;" :: "r"(dst), "l"(src));
}
__device__ __forceinline__ void cp_commit() {
    asm volatile("cp.async.commit_group;");
}
template <int N>
__device__ __forceinline__ void cp_wait() {
    asm volatile("cp.async.wait_group %0;" :: "n"(N));
}

// ---------------------------------------------------------------------------
// Pre-pass 1: elementwise fp32 -> fp16 for query/key/value.
// ---------------------------------------------------------------------------
__global__ void cvt_x_kernel(const float* __restrict__ q,
                             const float* __restrict__ k,
                             const float* __restrict__ v,
                             __half* __restrict__ dst) {
    const int z = blockIdx.z;
    const float* src = (z == 0) ? q : (z == 1) ? k : v;
    const float4* __restrict__ s4 = (const float4*)src;
    uint2* __restrict__ d4 = (uint2*)(dst + (size_t)z * BB * SS * HID);
    const int n4 = BB * SS * HID / 4;
    for (int i = blockIdx.x * blockDim.x + threadIdx.x; i < n4;
         i += gridDim.x * blockDim.x) {
        float4 vv = s4[i];
        uint2 o;
        o.x = pack2(vv.x, vv.y);
        o.y = pack2(vv.z, vv.w);
        d4[i] = o;
    }
}

// Pre-pass 2: transpose W [k][n] fp32 -> Wt [n][k] fp16. grid.z = 4 tensors.
__global__ void transpose_w_kernel(const float* __restrict__ Wq,
                                   const float* __restrict__ Wk,
                                   const float* __restrict__ Wv,
                                   const float* __restrict__ Wo,
                                   __half* __restrict__ dst) {
    __shared__ float t[32][33];
    const int z = blockIdx.z;
    const float* W = (z == 0) ? Wq : (z == 1) ? Wk : (z == 2) ? Wv : Wo;
    __half* Wt = dst + (size_t)z * HID * INNER;
    const int x0 = blockIdx.x * 32, y0 = blockIdx.y * 32;
    const int tx = threadIdx.x, ty = threadIdx.y;
#pragma unroll
    for (int i = 0; i < 4; i++)
        t[ty + i * 8][tx] = W[(size_t)(y0 + ty + i * 8) * INNER + x0 + tx];
    __syncthreads();
#pragma unroll
    for (int i = 0; i < 4; i++)
        Wt[(size_t)(x0 + ty + i * 8) * HID + y0 + tx] = hrn(t[tx][ty + i * 8]);
}

// ---------------------------------------------------------------------------
// fp16 GEMM (unchanged from R13/R14).
// ---------------------------------------------------------------------------
#define AHS 40
#define ABT (128*AHS)
#define GEMM_SMEM (4*ABT*2)          // 40960 bytes

template <int MODE>
__device__ __forceinline__ void gemm_body(const __half* __restrict__ X,
                                          const __half* __restrict__ Wt,
                                          const float* __restrict__ bias,
                                          void* __restrict__ outv,
                                          int m0, int n0) {
    extern __shared__ __align__(16) char smc[];
    __half* As = (__half*)smc;
    __half* Bs = As + 2 * ABT;

    const int tid  = threadIdx.x;
    const int lane = tid & 31;
    const int wid  = tid >> 5;
    const int wm   = (wid >> 2) * 64;
    const int wn   = (wid & 3) * 32;

    const int cr = tid >> 2, cch = tid & 3;
    const uint32_t asm0 = smaddr(As);
    const uint32_t bsm0 = smaddr(Bs);

    float c[4][4][4] = {};

#pragma unroll
    for (int i = 0; i < 2; i++) {
        int r = cr + i * 64;
        cp16(asm0 + r * (AHS * 2) + cch * 16, X + (size_t)(m0 + r) * HID + cch * 8);
        cp16(bsm0 + r * (AHS * 2) + cch * 16, Wt + (size_t)(n0 + r) * HID + cch * 8);
    }
    cp_commit();

    const int NT = HID / 32;
    for (int t = 0; t < NT; t++) {
        const int kt = t * 32;
        const int cur = t & 1;
        if (t + 1 < NT) {
            const int nxt = (t + 1) & 1;
#pragma unroll
            for (int i = 0; i < 2; i++) {
                int r = cr + i * 64;
                cp16(asm0 + nxt * ABT * 2 + r * (AHS * 2) + cch * 16,
                     X + (size_t)(m0 + r) * HID + kt + 32 + cch * 8);
                cp16(bsm0 + nxt * ABT * 2 + r * (AHS * 2) + cch * 16,
                     Wt + (size_t)(n0 + r) * HID + kt + 32 + cch * 8);
            }
            cp_commit();
            cp_wait<1>();
        } else {
            cp_wait<0>();
        }
        __syncthreads();

        const uint32_t* A32 = (const uint32_t*)(As + cur * ABT);
        const uint32_t* B32 = (const uint32_t*)(Bs + cur * ABT);
#pragma unroll
        for (int kk = 0; kk < 2; kk++) {
            uint32_t af[4][4], bf[4][2];
            const int ko = kk * 8 + (lane & 3);
#pragma unroll
            for (int mf = 0; mf < 4; mf++) {
                int row = wm + mf * 16 + (lane >> 2);
                af[mf][0] = A32[row * 20 + ko];
                af[mf][1] = A32[(row + 8) * 20 + ko];
                af[mf][2] = A32[row * 20 + ko + 4];
                af[mf][3] = A32[(row + 8) * 20 + ko + 4];
            }
#pragma unroll
            for (int nf = 0; nf < 4; nf++) {
                int n = wn + nf * 8 + (lane >> 2);
                bf[nf][0] = B32[n * 20 + ko];
                bf[nf][1] = B32[n * 20 + ko + 4];
            }
#pragma unroll
            for (int mf = 0; mf < 4; mf++)
#pragma unroll
                for (int nf = 0; nf < 4; nf++)
                    mma16(c[mf][nf], af[mf], bf[nf]);
        }
        __syncthreads();
    }

#pragma unroll
    for (int mf = 0; mf < 4; mf++) {
#pragma unroll
        for (int nf = 0; nf < 4; nf++) {
            int row = m0 + wm + mf * 16 + (lane >> 2);
            int col = n0 + wn + nf * 8 + (lane & 3) * 2;
            float v00 = c[mf][nf][0] + bias[col];
            float v01 = c[mf][nf][1] + bias[col + 1];
            float v10 = c[mf][nf][2] + bias[col];
            float v11 = c[mf][nf][3] + bias[col + 1];
            if (MODE == 0) {
                float* out = (float*)outv;
                *(float2*)(out + (size_t)row * INNER + col) = make_float2(v00, v01);
                *(float2*)(out + (size_t)(row + 8) * INNER + col) = make_float2(v10, v11);
            } else {
                int b = row >> 11, s = row & 2047;
                int h = col >> 6, d = col & 63;
                __half* out = (__half*)outv;
                if (MODE == 1) {
                    *(uint32_t*)(out + (((size_t)(b * HEADS + h)) * SS + s) * DHEAD + d) =
                        pack2(v00, v01);
                    *(uint32_t*)(out + (((size_t)(b * HEADS + h)) * SS + s + 8) * DHEAD + d) =
                        pack2(v10, v11);
                } else {
                    __half* base = out + ((size_t)(b * HEADS + h)) * DHEAD * SS;
                    base[(size_t)d * SS + s]           = hrn(v00);
                    base[(size_t)(d + 1) * SS + s]     = hrn(v01);
                    base[(size_t)d * SS + s + 8]       = hrn(v10);
                    base[(size_t)(d + 1) * SS + s + 8] = hrn(v11);
                }
            }
        }
    }
}

__global__ void __launch_bounds__(256)
gemm_qkv(const __half* __restrict__ rx, const __half* __restrict__ rw,
         const float* __restrict__ bq, const float* __restrict__ bk,
         const float* __restrict__ bv,
         __half* __restrict__ oq, __half* __restrict__ ok, __half* __restrict__ ov) {
    const int z = blockIdx.z;
    const __half* X = rx + (size_t)z * BB * SS * HID;
    const __half* W = rw + (size_t)z * HID * INNER;
    const float* bs = (z == 0) ? bq : (z == 1) ? bk : bv;
    if (z == 2)
        gemm_body<2>(X, W, bs, ov, blockIdx.y * 128, blockIdx.x * 128);
    else
        gemm_body<1>(X, W, bs, (z == 0) ? oq : ok, blockIdx.y * 128, blockIdx.x * 128);
}

__global__ void __launch_bounds__(256)
gemm_out(const __half* __restrict__ A, const __half* __restrict__ Wt,
         const float* __restrict__ bias, float* __restrict__ out) {
    gemm_body<0>(A, Wt, bias, out, blockIdx.y * 128, blockIdx.x * 128);
}

// ---------------------------------------------------------------------------
// Warp-specialized flash attention. fp16 mma, no max-shift, P in registers,
// K/V via ldmatrix, fp16x2 softmax (HFMA2 + ex2.approx.f16x2), row sums via
// ones-column MMA. cb staged as half2 pre-scaled by log2e.
// 256 threads: warps 0-3 consumers, 4-7 producers. 2 CTAs/SM.
// ---------------------------------------------------------------------------
#define KVS 72
#define KVROW_B (KVS*2)               // 144 bytes per K/V smem row
#define KVH_T (2 * 64 * KVS)          // 9216 halves per KV buffer
#define CB_T (64 * 68)                // halves per cb buffer
#define QHS 72
// bytes: KV 2*9216*2=36864 | CB 2*4352*2=17408 | Q 64*72*2=9216 -> 63488
#define ATTN_SMEM (2*KVH_T*2 + 2*CB_T*2 + 64*QHS*2)

__global__ void __launch_bounds__(256, 2)
attn_fp16(const float* __restrict__ bias, const float* __restrict__ mask) {
    extern __shared__ __align__(16) char smc[];
    __half* KV  = (__half*)smc;
    __half* CBh = (__half*)(smc + 2 * KVH_T * 2);
    __half* Qs  = (__half*)(smc + 2 * KVH_T * 2 + 2 * CB_T * 2);

    const int tid  = threadIdx.x;
    const int lane = tid & 31;
    const int wid  = tid >> 5;
    const bool consumer = (wid < 4);
    const int bh   = blockIdx.y;
    const int b    = bh >> 4, h = bh & 15;
    const int q0   = blockIdx.x * 64;

    const __half* qp = g_q + (size_t)bh * SS * DHEAD;
    const __half* kp = g_k + (size_t)bh * SS * DHEAD;
    const __half* vtp = g_v + (size_t)bh * DHEAD * SS;

    const int NT = SS / 64;

    if (consumer) {
#pragma unroll
        for (int i = 0; i < 4; i++) {
            int idx = tid + i * 128;
            int r = idx >> 3, ch = idx & 7;
            *(uint4*)(Qs + r * QHS + ch * 8) =
                *(const uint4*)(qp + (size_t)(q0 + r) * DHEAD + ch * 8);
        }
    } else {
        const int ptid = tid - 128;
        const int cr = ptid >> 3, cch = ptid & 7;
        uint32_t kd = smaddr(KV);
        uint32_t vd = kd + 64 * KVROW_B;
#pragma unroll
        for (int i = 0; i < 4; i++) {
            int r = cr + i * 16;
            cp16(kd + r * KVROW_B + cch * 16, kp + (size_t)r * DHEAD + cch * 8);
            cp16(vd + r * KVROW_B + cch * 16, vtp + (size_t)r * SS + cch * 8);
        }
        cp_commit();
        const int pwid = wid - 4;
        const int rbase = pwid * 16;
        const int rr = lane >> 4, c4 = (lane & 15) * 4;
        const float* bp = bias + ((size_t)h * SS + q0 + rbase) * SS;
        const float* mp = mask + ((size_t)b * SS + q0 + rbase) * SS;
#pragma unroll
        for (int i = 0; i < 8; i++) {
            int r = i * 2 + rr;
            float4 bv4 = *(const float4*)&bp[(size_t)r * SS + c4];
            float4 mv4 = *(const float4*)&mp[(size_t)r * SS + c4];
            uint2 cb;
            cb.x = pack2((bv4.x * 0.125f + mv4.x) * LOG2E,
                         (bv4.y * 0.125f + mv4.y) * LOG2E);
            cb.y = pack2((bv4.z * 0.125f + mv4.z) * LOG2E,
                         (bv4.w * 0.125f + mv4.w) * LOG2E);
            *(uint2*)&CBh[(rbase + r) * 68 + c4] = cb;
        }
        cp_wait<0>();
    }
    __syncthreads();

    uint32_t qf[4][4];
    float osum[4] = {0.f, 0.f, 0.f, 0.f};   // row sums via ones-MMA
    float o[8][4] = {};
    const int grow0 = q0 + (wid & 3) * 16 + (lane >> 2);
    const int lr = lane >> 2;
    const int jrow = lane & 7;
    const int jlo  = (lane >> 3) & 1;
    const int jhi  = (lane >> 4) & 1;
    const uint32_t scl2 = pack2(0.125f * LOG2E, 0.125f * LOG2E);
    const uint32_t ones2 = 0x3C003C00u;      // half2(1.0, 1.0)
    const uint32_t bones[2] = {ones2, ones2};

    if (consumer) {
        const uint32_t* Q32 = (const uint32_t*)Qs;
        int qrow = wid * 16 + (lane >> 2);
#pragma unroll
        for (int kk = 0; kk < 4; kk++) {
            int ko = kk * 8 + (lane & 3);
            qf[kk][0] = Q32[qrow * 36 + ko];
            qf[kk][1] = Q32[(qrow + 8) * 36 + ko];
            qf[kk][2] = Q32[qrow * 36 + ko + 4];
            qf[kk][3] = Q32[(qrow + 8) * 36 + ko + 4];
        }
    }

    for (int t = 0; t < NT; t++) {
        if (consumer) {
            const uint32_t ksb = smaddr(KV) + (t & 1) * KVH_T * 2;
            const uint32_t vsb = ksb + 64 * KVROW_B;
            const __half* Cw = CBh + (t & 1) * CB_T + wid * 16 * 68;

            // scores = Q @ K^T
            float s[8][4] = {};
#pragma unroll
            for (int kk = 0; kk < 4; kk++) {
                uint32_t bf[8][2];
#pragma unroll
                for (int np = 0; np < 4; np++) {
                    uint32_t addr = ksb + (np * 16 + jhi * 8 + jrow) * KVROW_B
                                  + kk * 32 + jlo * 16;
                    ldm4(bf[2 * np][0], bf[2 * np][1],
                         bf[2 * np + 1][0], bf[2 * np + 1][1], addr);
                }
#pragma unroll
                for (int nf = 0; nf < 8; nf++)
                    mma16(s[nf], qf[kk], bf[nf]);
            }

            // P = 2^(s*0.125*log2e + cb)  -- half2 HFMA2 + EX2.f16x2.
            uint32_t pp[8][2];
#pragma unroll
            for (int nf = 0; nf < 8; nf++) {
                int col = nf * 8 + (lane & 3) * 2;
                uint32_t c0 = *(const uint32_t*)&Cw[lr * 68 + col];
                uint32_t c1 = *(const uint32_t*)&Cw[(lr + 8) * 68 + col];
                uint32_t sh0 = pack2(s[nf][0], s[nf][1]);
                uint32_t sh1 = pack2(s[nf][2], s[nf][3]);
                uint32_t x0, x1;
                asm("fma.rn.f16x2 %0, %1, %2, %3;"
                    : "=r"(x0) : "r"(sh0), "r"(scl2), "r"(c0));
                asm("fma.rn.f16x2 %0, %1, %2, %3;"
                    : "=r"(x1) : "r"(sh1), "r"(scl2), "r"(c1));
                asm("ex2.approx.f16x2 %0, %1;" : "=r"(pp[nf][0]) : "r"(x0));
                asm("ex2.approx.f16x2 %0, %1;" : "=r"(pp[nf][1]) : "r"(x1));
            }

            // o += P @ V ; osum += P @ ones (row sums, exact fp32 accumulate)
#pragma unroll
            for (int kk = 0; kk < 4; kk++) {
                uint32_t vb[8][2];
#pragma unroll
                for (int dp = 0; dp < 4; dp++) {
                    uint32_t addr = vsb + (dp * 16 + jhi * 8 + jrow) * KVROW_B
                                  + kk * 32 + jlo * 16;
                    ldm4(vb[2 * dp][0], vb[2 * dp][1],
                         vb[2 * dp + 1][0], vb[2 * dp + 1][1], addr);
                }
                uint32_t pa[4] = {pp[2 * kk][0], pp[2 * kk][1],
                                  pp[2 * kk + 1][0], pp[2 * kk + 1][1]};
#pragma unroll
                for (int df = 0; df < 8; df++)
                    mma16(o[df], pa, vb[df]);
                mma16(osum, pa, bones);
            }
        } else if (t + 1 < NT) {
            const int kt1 = (t + 1) * 64;
            const int ptid = tid - 128;
            const int cr = ptid >> 3, cch = ptid & 7;
            uint32_t kd = smaddr(KV) + ((t + 1) & 1) * KVH_T * 2;
            uint32_t vd = kd + 64 * KVROW_B;
#pragma unroll
            for (int i = 0; i < 4; i++) {
                int r = cr + i * 16;
                cp16(kd + r * KVROW_B + cch * 16,
                     kp + (size_t)(kt1 + r) * DHEAD + cch * 8);
                cp16(vd + r * KVROW_B + cch * 16,
                     vtp + (size_t)r * SS + kt1 + cch * 8);
            }
            cp_commit();

            const int pwid = wid - 4;
            const int rbase = pwid * 16;
            const int rr = lane >> 4, c4 = (lane & 15) * 4;
            __half* cbb = CBh + ((t + 1) & 1) * CB_T;
            const float* bp = bias + ((size_t)h * SS + q0 + rbase) * SS + kt1;
            const float* mp = mask + ((size_t)b * SS + q0 + rbase) * SS + kt1;
#pragma unroll
            for (int i = 0; i < 8; i++) {
                int r = i * 2 + rr;
                float4 bv4 = *(const float4*)&bp[(size_t)r * SS + c4];
                float4 mv4 = *(const float4*)&mp[(size_t)r * SS + c4];
                uint2 cb;
                cb.x = pack2((bv4.x * 0.125f + mv4.x) * LOG2E,
                             (bv4.y * 0.125f + mv4.y) * LOG2E);
                cb.y = pack2((bv4.z * 0.125f + mv4.z) * LOG2E,
                             (bv4.w * 0.125f + mv4.w) * LOG2E);
                *(uint2*)&cbb[(rbase + r) * 68 + c4] = cb;
            }
            cp_wait<0>();
        }
        __syncthreads();
    }

    if (consumer) {
        // osum[0]==rowsum(lr), osum[2]==rowsum(lr+8) (ones-MMA, no shuffle).
        float inv0 = 1.f / osum[0], inv1 = 1.f / osum[2];
#pragma unroll
        for (int df = 0; df < 8; df++) {
            int colg = h * 64 + df * 8 + (lane & 3) * 2;
            *(uint32_t*)(g_att + ((size_t)b * SS + grow0) * INNER + colg) =
                pack2(o[df][0] * inv0, o[df][1] * inv0);
            *(uint32_t*)(g_att + ((size_t)b * SS + grow0 + 8) * INNER + colg) =
                pack2(o[df][2] * inv1, o[df][3] * inv1);
        }
    }
}

// ---------------------------------------------------------------------------

extern "C" void kernel_launch(void* const* d_in, const int* in_sizes, int n_in,
                              void* d_out, int out_size) {
    const float* query = (const float*)d_in[0];
    const float* key_i = (const float*)d_in[1];
    const float* value = (const float*)d_in[2];
    const float* mask  = (const float*)d_in[3];
    const float* pbias = (const float*)d_in[4];
    const float* Wq = (const float*)d_in[5];
    const float* bq = (const float*)d_in[6];
    const float* Wk = (const float*)d_in[7];
    const float* bk = (const float*)d_in[8];
    const float* Wv = (const float*)d_in[9];
    const float* bv = (const float*)d_in[10];
    const float* Wo = (const float*)d_in[11];
    const float* bo = (const float*)d_in[12];
    float* out = (float*)d_out;

    __half *qb, *kb, *vb, *ab, *rw, *rx;
    cudaGetSymbolAddress((void**)&qb, g_q);
    cudaGetSymbolAddress((void**)&kb, g_k);
    cudaGetSymbolAddress((void**)&vb, g_v);
    cudaGetSymbolAddress((void**)&ab, g_att);
    cudaGetSymbolAddress((void**)&rw, g_rw);
    cudaGetSymbolAddress((void**)&rx, g_rx);

    dim3 grid_cvt(256, 1, 3);
    cvt_x_kernel<<<grid_cvt, 256>>>(query, key_i, value, rx);
    dim3 grid_tr(INNER / 32, HID / 32, 4);
    transpose_w_kernel<<<grid_tr, dim3(32, 8)>>>(Wq, Wk, Wv, Wo, rw);

    cudaFuncSetAttribute(gemm_qkv, cudaFuncAttributeMaxDynamicSharedMemorySize, GEMM_SMEM);
    cudaFuncSetAttribute(gemm_out, cudaFuncAttributeMaxDynamicSharedMemorySize, GEMM_SMEM);
    dim3 grid_qkv(INNER / 128, (BB * SS) / 128, 3);
    gemm_qkv<<<grid_qkv, 256, GEMM_SMEM>>>(rx, rw, bq, bk, bv, qb, kb, vb);

    cudaFuncSetAttribute(attn_fp16, cudaFuncAttributeMaxDynamicSharedMemorySize, ATTN_SMEM);
    dim3 grid_attn(SS / 64, BH);     // (32, 32), 2 CTAs/SM
    attn_fp16<<<grid_attn, 256, ATTN_SMEM>>>(pbias, mask);

    dim3 grid_gemm(INNER / 128, (BB * SS) / 128);
    gemm_out<<<grid_gemm, 256, GEMM_SMEM>>>(ab, rw + 3 * (size_t)HID * INNER, bo, out);
}

// round 16
// speedup vs baseline: 1.0070x; 1.0070x over previous
#include <cuda_runtime.h>
#include <cuda_fp16.h>
#include <math.h>
#include <stdint.h>

#define BB 2
#define SS 2048
#define HID 1024
#define HEADS 16
#define DHEAD 64
#define INNER 1024
#define BH (BB*HEADS)

// Scratch (fp16). q,k in [B,H,S,D]; v TRANSPOSED [B,H,D,S]; att [B,S,INNER].
__device__ __half g_q[BB*HEADS*SS*DHEAD];
__device__ __half g_k[BB*HEADS*SS*DHEAD];
__device__ __half g_v[BB*HEADS*SS*DHEAD];
__device__ __half g_att[BB*SS*INNER];
__device__ __half g_rw[4*HID*INNER];   // Wq,Wk,Wv,Wo TRANSPOSED [n][k] fp16
__device__ __half g_rx[3*BB*SS*HID];   // query,key,value fp16

#define LOG2E 1.4426950408889634f

__device__ __forceinline__ __half hrn(float x) { return __float2half_rn(x); }

__device__ __forceinline__ uint32_t pack2(float a, float b) {
    __half2 h = __halves2half2(hrn(a), hrn(b));
    uint32_t u;
    *(__half2*)&u = h;
    return u;
}

__device__ __forceinline__ void mma16(float* c, const uint32_t* a, const uint32_t* b) {
    asm volatile(
        "mma.sync.aligned.m16n8k16.row.col.f32.f16.f16.f32 "
        "{%0,%1,%2,%3}, {%4,%5,%6,%7}, {%8,%9}, {%0,%1,%2,%3};"
        : "+f"(c[0]), "+f"(c[1]), "+f"(c[2]), "+f"(c[3])
        : "r"(a[0]), "r"(a[1]), "r"(a[2]), "r"(a[3]), "r"(b[0]), "r"(b[1]));
}

__device__ __forceinline__ void ldm4(uint32_t& r0, uint32_t& r1, uint32_t& r2,
                                     uint32_t& r3, uint32_t addr) {
    asm volatile(
        "ldmatrix.sync.aligned.m8n8.x4.shared.b16 {%0,%1,%2,%3}, [%4];"
        : "=r"(r0), "=r"(r1), "=r"(r2), "=r"(r3) : "r"(addr));
}

__device__ __forceinline__ uint32_t smaddr(const void* p) {
    return (uint32_t)__cvta_generic_to_shared(p);
}
__device__ __forceinline__ void cp16(uint32_t dst, const void* src) {
    asm volatile("cp.async.cg.shared.global [%0], [%1], 16;" :: "r"(dst), "l"(src));
}
__device__ __forceinline__ void cp_commit() {
    asm volatile("cp.async.commit_group;");
}
template <int N>
__device__ __forceinline__ void cp_wait() {
    asm volatile("cp.async.wait_group %0;" :: "n"(N));
}

// ---------------------------------------------------------------------------
// Pre-pass 1: elementwise fp32 -> fp16 for query/key/value.
// ---------------------------------------------------------------------------
__global__ void cvt_x_kernel(const float* __restrict__ q,
                             const float* __restrict__ k,
                             const float* __restrict__ v,
                             __half* __restrict__ dst) {
    const int z = blockIdx.z;
    const float* src = (z == 0) ? q : (z == 1) ? k : v;
    const float4* __restrict__ s4 = (const float4*)src;
    uint2* __restrict__ d4 = (uint2*)(dst + (size_t)z * BB * SS * HID);
    const int n4 = BB * SS * HID / 4;
    for (int i = blockIdx.x * blockDim.x + threadIdx.x; i < n4;
         i += gridDim.x * blockDim.x) {
        float4 vv = s4[i];
        uint2 o;
        o.x = pack2(vv.x, vv.y);
        o.y = pack2(vv.z, vv.w);
        d4[i] = o;
    }
}

// Pre-pass 2: transpose W [k][n] fp32 -> Wt [n][k] fp16. grid.z = 4 tensors.
__global__ void transpose_w_kernel(const float* __restrict__ Wq,
                                   const float* __restrict__ Wk,
                                   const float* __restrict__ Wv,
                                   const float* __restrict__ Wo,
                                   __half* __restrict__ dst) {
    __shared__ float t[32][33];
    const int z = blockIdx.z;
    const float* W = (z == 0) ? Wq : (z == 1) ? Wk : (z == 2) ? Wv : Wo;
    __half* Wt = dst + (size_t)z * HID * INNER;
    const int x0 = blockIdx.x * 32, y0 = blockIdx.y * 32;
    const int tx = threadIdx.x, ty = threadIdx.y;
#pragma unroll
    for (int i = 0; i < 4; i++)
        t[ty + i * 8][tx] = W[(size_t)(y0 + ty + i * 8) * INNER + x0 + tx];
    __syncthreads();
#pragma unroll
    for (int i = 0; i < 4; i++)
        Wt[(size_t)(x0 + ty + i * 8) * HID + y0 + tx] = hrn(t[tx][ty + i * 8]);
}

// ---------------------------------------------------------------------------
// fp16 GEMM (unchanged).
// ---------------------------------------------------------------------------
#define AHS 40
#define ABT (128*AHS)
#define GEMM_SMEM (4*ABT*2)          // 40960 bytes

template <int MODE>
__device__ __forceinline__ void gemm_body(const __half* __restrict__ X,
                                          const __half* __restrict__ Wt,
                                          const float* __restrict__ bias,
                                          void* __restrict__ outv,
                                          int m0, int n0) {
    extern __shared__ __align__(16) char smc[];
    __half* As = (__half*)smc;
    __half* Bs = As + 2 * ABT;

    const int tid  = threadIdx.x;
    const int lane = tid & 31;
    const int wid  = tid >> 5;
    const int wm   = (wid >> 2) * 64;
    const int wn   = (wid & 3) * 32;

    const int cr = tid >> 2, cch = tid & 3;
    const uint32_t asm0 = smaddr(As);
    const uint32_t bsm0 = smaddr(Bs);

    float c[4][4][4] = {};

#pragma unroll
    for (int i = 0; i < 2; i++) {
        int r = cr + i * 64;
        cp16(asm0 + r * (AHS * 2) + cch * 16, X + (size_t)(m0 + r) * HID + cch * 8);
        cp16(bsm0 + r * (AHS * 2) + cch * 16, Wt + (size_t)(n0 + r) * HID + cch * 8);
    }
    cp_commit();

    const int NT = HID / 32;
    for (int t = 0; t < NT; t++) {
        const int kt = t * 32;
        const int cur = t & 1;
        if (t + 1 < NT) {
            const int nxt = (t + 1) & 1;
#pragma unroll
            for (int i = 0; i < 2; i++) {
                int r = cr + i * 64;
                cp16(asm0 + nxt * ABT * 2 + r * (AHS * 2) + cch * 16,
                     X + (size_t)(m0 + r) * HID + kt + 32 + cch * 8);
                cp16(bsm0 + nxt * ABT * 2 + r * (AHS * 2) + cch * 16,
                     Wt + (size_t)(n0 + r) * HID + kt + 32 + cch * 8);
            }
            cp_commit();
            cp_wait<1>();
        } else {
            cp_wait<0>();
        }
        __syncthreads();

        const uint32_t* A32 = (const uint32_t*)(As + cur * ABT);
        const uint32_t* B32 = (const uint32_t*)(Bs + cur * ABT);
#pragma unroll
        for (int kk = 0; kk < 2; kk++) {
            uint32_t af[4][4], bf[4][2];
            const int ko = kk * 8 + (lane & 3);
#pragma unroll
            for (int mf = 0; mf < 4; mf++) {
                int row = wm + mf * 16 + (lane >> 2);
                af[mf][0] = A32[row * 20 + ko];
                af[mf][1] = A32[(row + 8) * 20 + ko];
                af[mf][2] = A32[row * 20 + ko + 4];
                af[mf][3] = A32[(row + 8) * 20 + ko + 4];
            }
#pragma unroll
            for (int nf = 0; nf < 4; nf++) {
                int n = wn + nf * 8 + (lane >> 2);
                bf[nf][0] = B32[n * 20 + ko];
                bf[nf][1] = B32[n * 20 + ko + 4];
            }
#pragma unroll
            for (int mf = 0; mf < 4; mf++)
#pragma unroll
                for (int nf = 0; nf < 4; nf++)
                    mma16(c[mf][nf], af[mf], bf[nf]);
        }
        __syncthreads();
    }

#pragma unroll
    for (int mf = 0; mf < 4; mf++) {
#pragma unroll
        for (int nf = 0; nf < 4; nf++) {
            int row = m0 + wm + mf * 16 + (lane >> 2);
            int col = n0 + wn + nf * 8 + (lane & 3) * 2;
            float v00 = c[mf][nf][0] + bias[col];
            float v01 = c[mf][nf][1] + bias[col + 1];
            float v10 = c[mf][nf][2] + bias[col];
            float v11 = c[mf][nf][3] + bias[col + 1];
            if (MODE == 0) {
                float* out = (float*)outv;
                *(float2*)(out + (size_t)row * INNER + col) = make_float2(v00, v01);
                *(float2*)(out + (size_t)(row + 8) * INNER + col) = make_float2(v10, v11);
            } else {
                int b = row >> 11, s = row & 2047;
                int h = col >> 6, d = col & 63;
                __half* out = (__half*)outv;
                if (MODE == 1) {
                    *(uint32_t*)(out + (((size_t)(b * HEADS + h)) * SS + s) * DHEAD + d) =
                        pack2(v00, v01);
                    *(uint32_t*)(out + (((size_t)(b * HEADS + h)) * SS + s + 8) * DHEAD + d) =
                        pack2(v10, v11);
                } else {
                    __half* base = out + ((size_t)(b * HEADS + h)) * DHEAD * SS;
                    base[(size_t)d * SS + s]           = hrn(v00);
                    base[(size_t)(d + 1) * SS + s]     = hrn(v01);
                    base[(size_t)d * SS + s + 8]       = hrn(v10);
                    base[(size_t)(d + 1) * SS + s + 8] = hrn(v11);
                }
            }
        }
    }
}

__global__ void __launch_bounds__(256)
gemm_qkv(const __half* __restrict__ rx, const __half* __restrict__ rw,
         const float* __restrict__ bq, const float* __restrict__ bk,
         const float* __restrict__ bv,
         __half* __restrict__ oq, __half* __restrict__ ok, __half* __restrict__ ov) {
    const int z = blockIdx.z;
    const __half* X = rx + (size_t)z * BB * SS * HID;
    const __half* W = rw + (size_t)z * HID * INNER;
    const float* bs = (z == 0) ? bq : (z == 1) ? bk : bv;
    if (z == 2)
        gemm_body<2>(X, W, bs, ov, blockIdx.y * 128, blockIdx.x * 128);
    else
        gemm_body<1>(X, W, bs, (z == 0) ? oq : ok, blockIdx.y * 128, blockIdx.x * 128);
}

__global__ void __launch_bounds__(256)
gemm_out(const __half* __restrict__ A, const __half* __restrict__ Wt,
         const float* __restrict__ bias, float* __restrict__ out) {
    gemm_body<0>(A, Wt, bias, out, blockIdx.y * 128, blockIdx.x * 128);
}

// ---------------------------------------------------------------------------
// Warp-specialized flash attention. fp16 mma, no max-shift, register P,
// ldmatrix K/V, fp16x2 softmax, ones-MMA row sums. Producer cb staging
// batched (8 LDG.128 in flight) to hide DRAM latency.
// 256 threads: warps 0-3 consumers, 4-7 producers. 2 CTAs/SM.
// ---------------------------------------------------------------------------
#define KVS 72
#define KVROW_B (KVS*2)               // 144 bytes per K/V smem row
#define KVH_T (2 * 64 * KVS)          // 9216 halves per KV buffer
#define CB_T (64 * 68)                // halves per cb buffer
#define QHS 72
#define ATTN_SMEM (2*KVH_T*2 + 2*CB_T*2 + 64*QHS*2)   // 63488

// Batched cb stage: 16 rows (one producer warp's share), loads grouped 4 rows
// (8 LDG.128) ahead of the dependent converts.
__device__ __forceinline__ void stage_cb(__half* cbb, const float* bp,
                                         const float* mp, int rbase,
                                         int rr, int c4) {
#pragma unroll
    for (int g = 0; g < 2; g++) {
        float4 bv4[4], mv4[4];
#pragma unroll
        for (int i = 0; i < 4; i++) {
            int r = (g * 4 + i) * 2 + rr;
            bv4[i] = *(const float4*)&bp[(size_t)r * SS + c4];
            mv4[i] = *(const float4*)&mp[(size_t)r * SS + c4];
        }
#pragma unroll
        for (int i = 0; i < 4; i++) {
            int r = (g * 4 + i) * 2 + rr;
            uint2 cb;
            cb.x = pack2((bv4[i].x * 0.125f + mv4[i].x) * LOG2E,
                         (bv4[i].y * 0.125f + mv4[i].y) * LOG2E);
            cb.y = pack2((bv4[i].z * 0.125f + mv4[i].z) * LOG2E,
                         (bv4[i].w * 0.125f + mv4[i].w) * LOG2E);
            *(uint2*)&cbb[(rbase + r) * 68 + c4] = cb;
        }
    }
}

__global__ void __launch_bounds__(256, 2)
attn_fp16(const float* __restrict__ bias, const float* __restrict__ mask) {
    extern __shared__ __align__(16) char smc[];
    __half* KV  = (__half*)smc;
    __half* CBh = (__half*)(smc + 2 * KVH_T * 2);
    __half* Qs  = (__half*)(smc + 2 * KVH_T * 2 + 2 * CB_T * 2);

    const int tid  = threadIdx.x;
    const int lane = tid & 31;
    const int wid  = tid >> 5;
    const bool consumer = (wid < 4);
    const int bh   = blockIdx.y;
    const int b    = bh >> 4, h = bh & 15;
    const int q0   = blockIdx.x * 64;

    const __half* qp = g_q + (size_t)bh * SS * DHEAD;
    const __half* kp = g_k + (size_t)bh * SS * DHEAD;
    const __half* vtp = g_v + (size_t)bh * DHEAD * SS;

    const int NT = SS / 64;

    if (consumer) {
#pragma unroll
        for (int i = 0; i < 4; i++) {
            int idx = tid + i * 128;
            int r = idx >> 3, ch = idx & 7;
            *(uint4*)(Qs + r * QHS + ch * 8) =
                *(const uint4*)(qp + (size_t)(q0 + r) * DHEAD + ch * 8);
        }
    } else {
        const int ptid = tid - 128;
        const int cr = ptid >> 3, cch = ptid & 7;
        uint32_t kd = smaddr(KV);
        uint32_t vd = kd + 64 * KVROW_B;
#pragma unroll
        for (int i = 0; i < 4; i++) {
            int r = cr + i * 16;
            cp16(kd + r * KVROW_B + cch * 16, kp + (size_t)r * DHEAD + cch * 8);
            cp16(vd + r * KVROW_B + cch * 16, vtp + (size_t)r * SS + cch * 8);
        }
        cp_commit();
        const int rbase = (wid - 4) * 16;
        const int rr = lane >> 4, c4 = (lane & 15) * 4;
        stage_cb(CBh, bias + ((size_t)h * SS + q0 + rbase) * SS,
                 mask + ((size_t)b * SS + q0 + rbase) * SS, rbase, rr, c4);
        cp_wait<0>();
    }
    __syncthreads();

    uint32_t qf[4][4];
    float osum[4] = {0.f, 0.f, 0.f, 0.f};
    float o[8][4] = {};
    const int grow0 = q0 + (wid & 3) * 16 + (lane >> 2);
    const int lr = lane >> 2;
    const int jrow = lane & 7;
    const int jlo  = (lane >> 3) & 1;
    const int jhi  = (lane >> 4) & 1;
    const uint32_t scl2 = pack2(0.125f * LOG2E, 0.125f * LOG2E);
    const uint32_t ones2 = 0x3C003C00u;
    const uint32_t bones[2] = {ones2, ones2};

    if (consumer) {
        const uint32_t* Q32 = (const uint32_t*)Qs;
        int qrow = wid * 16 + (lane >> 2);
#pragma unroll
        for (int kk = 0; kk < 4; kk++) {
            int ko = kk * 8 + (lane & 3);
            qf[kk][0] = Q32[qrow * 36 + ko];
            qf[kk][1] = Q32[(qrow + 8) * 36 + ko];
            qf[kk][2] = Q32[qrow * 36 + ko + 4];
            qf[kk][3] = Q32[(qrow + 8) * 36 + ko + 4];
        }
    }

    for (int t = 0; t < NT; t++) {
        if (consumer) {
            const uint32_t ksb = smaddr(KV) + (t & 1) * KVH_T * 2;
            const uint32_t vsb = ksb + 64 * KVROW_B;
            const __half* Cw = CBh + (t & 1) * CB_T + wid * 16 * 68;

            float s[8][4] = {};
#pragma unroll
            for (int kk = 0; kk < 4; kk++) {
                uint32_t bf[8][2];
#pragma unroll
                for (int np = 0; np < 4; np++) {
                    uint32_t addr = ksb + (np * 16 + jhi * 8 + jrow) * KVROW_B
                                  + kk * 32 + jlo * 16;
                    ldm4(bf[2 * np][0], bf[2 * np][1],
                         bf[2 * np + 1][0], bf[2 * np + 1][1], addr);
                }
#pragma unroll
                for (int nf = 0; nf < 8; nf++)
                    mma16(s[nf], qf[kk], bf[nf]);
            }

            uint32_t pp[8][2];
#pragma unroll
            for (int nf = 0; nf < 8; nf++) {
                int col = nf * 8 + (lane & 3) * 2;
                uint32_t c0 = *(const uint32_t*)&Cw[lr * 68 + col];
                uint32_t c1 = *(const uint32_t*)&Cw[(lr + 8) * 68 + col];
                uint32_t sh0 = pack2(s[nf][0], s[nf][1]);
                uint32_t sh1 = pack2(s[nf][2], s[nf][3]);
                uint32_t x0, x1;
                asm("fma.rn.f16x2 %0, %1, %2, %3;"
                    : "=r"(x0) : "r"(sh0), "r"(scl2), "r"(c0));
                asm("fma.rn.f16x2 %0, %1, %2, %3;"
                    : "=r"(x1) : "r"(sh1), "r"(scl2), "r"(c1));
                asm("ex2.approx.f16x2 %0, %1;" : "=r"(pp[nf][0]) : "r"(x0));
                asm("ex2.approx.f16x2 %0, %1;" : "=r"(pp[nf][1]) : "r"(x1));
            }

#pragma unroll
            for (int kk = 0; kk < 4; kk++) {
                uint32_t vb[8][2];
#pragma unroll
                for (int dp = 0; dp < 4; dp++) {
                    uint32_t addr = vsb + (dp * 16 + jhi * 8 + jrow) * KVROW_B
                                  + kk * 32 + jlo * 16;
                    ldm4(vb[2 * dp][0], vb[2 * dp][1],
                         vb[2 * dp + 1][0], vb[2 * dp + 1][1], addr);
                }
                uint32_t pa[4] = {pp[2 * kk][0], pp[2 * kk][1],
                                  pp[2 * kk + 1][0], pp[2 * kk + 1][1]};
#pragma unroll
                for (int df = 0; df < 8; df++)
                    mma16(o[df], pa, vb[df]);
                mma16(osum, pa, bones);
            }
        } else if (t + 1 < NT) {
            const int kt1 = (t + 1) * 64;
            const int ptid = tid - 128;
            const int cr = ptid >> 3, cch = ptid & 7;
            uint32_t kd = smaddr(KV) + ((t + 1) & 1) * KVH_T * 2;
            uint32_t vd = kd + 64 * KVROW_B;
#pragma unroll
            for (int i = 0; i < 4; i++) {
                int r = cr + i * 16;
                cp16(kd + r * KVROW_B + cch * 16,
                     kp + (size_t)(kt1 + r) * DHEAD + cch * 8);
                cp16(vd + r * KVROW_B + cch * 16,
                     vtp + (size_t)r * SS + kt1 + cch * 8);
            }
            cp_commit();

            const int rbase = (wid - 4) * 16;
            const int rr = lane >> 4, c4 = (lane & 15) * 4;
            stage_cb(CBh + ((t + 1) & 1) * CB_T,
                     bias + ((size_t)h * SS + q0 + rbase) * SS + kt1,
                     mask + ((size_t)b * SS + q0 + rbase) * SS + kt1,
                     rbase, rr, c4);
            cp_wait<0>();
        }
        __syncthreads();
    }

    if (consumer) {
        float inv0 = 1.f / osum[0], inv1 = 1.f / osum[2];
#pragma unroll
        for (int df = 0; df < 8; df++) {
            int colg = h * 64 + df * 8 + (lane & 3) * 2;
            *(uint32_t*)(g_att + ((size_t)b * SS + grow0) * INNER + colg) =
                pack2(o[df][0] * inv0, o[df][1] * inv0);
            *(uint32_t*)(g_att + ((size_t)b * SS + grow0 + 8) * INNER + colg) =
                pack2(o[df][2] * inv1, o[df][3] * inv1);
        }
    }
}

// ---------------------------------------------------------------------------

extern "C" void kernel_launch(void* const* d_in, const int* in_sizes, int n_in,
                              void* d_out, int out_size) {
    const float* query = (const float*)d_in[0];
    const float* key_i = (const float*)d_in[1];
    const float* value = (const float*)d_in[2];
    const float* mask  = (const float*)d_in[3];
    const float* pbias = (const float*)d_in[4];
    const float* Wq = (const float*)d_in[5];
    const float* bq = (const float*)d_in[6];
    const float* Wk = (const float*)d_in[7];
    const float* bk = (const float*)d_in[8];
    const float* Wv = (const float*)d_in[9];
    const float* bv = (const float*)d_in[10];
    const float* Wo = (const float*)d_in[11];
    const float* bo = (const float*)d_in[12];
    float* out = (float*)d_out;

    __half *qb, *kb, *vb, *ab, *rw, *rx;
    cudaGetSymbolAddress((void**)&qb, g_q);
    cudaGetSymbolAddress((void**)&kb, g_k);
    cudaGetSymbolAddress((void**)&vb, g_v);
    cudaGetSymbolAddress((void**)&ab, g_att);
    cudaGetSymbolAddress((void**)&rw, g_rw);
    cudaGetSymbolAddress((void**)&rx, g_rx);

    dim3 grid_cvt(256, 1, 3);
    cvt_x_kernel<<<grid_cvt, 256>>>(query, key_i, value, rx);
    dim3 grid_tr(INNER / 32, HID / 32, 4);
    transpose_w_kernel<<<grid_tr, dim3(32, 8)>>>(Wq, Wk, Wv, Wo, rw);

    cudaFuncSetAttribute(gemm_qkv, cudaFuncAttributeMaxDynamicSharedMemorySize, GEMM_SMEM);
    cudaFuncSetAttribute(gemm_out, cudaFuncAttributeMaxDynamicSharedMemorySize, GEMM_SMEM);
    dim3 grid_qkv(INNER / 128, (BB * SS) / 128, 3);
    gemm_qkv<<<grid_qkv, 256, GEMM_SMEM>>>(rx, rw, bq, bk, bv, qb, kb, vb);

    cudaFuncSetAttribute(attn_fp16, cudaFuncAttributeMaxDynamicSharedMemorySize, ATTN_SMEM);
    dim3 grid_attn(SS / 64, BH);     // (32, 32), 2 CTAs/SM
    attn_fp16<<<grid_attn, 256, ATTN_SMEM>>>(pbias, mask);

    dim3 grid_gemm(INNER / 128, (BB * SS) / 128);
    gemm_out<<<grid_gemm, 256, GEMM_SMEM>>>(ab, rw + 3 * (size_t)HID * INNER, bo, out);
}

// round 17
// speedup vs baseline: 1.1124x; 1.1046x over previous
#include <cuda_runtime.h>
#include <cuda_fp16.h>
#include <math.h>
#include <stdint.h>

#define BB 2
#define SS 2048
#define HID 1024
#define HEADS 16
#define DHEAD 64
#define INNER 1024
#define BH (BB*HEADS)

// Scratch (fp16). q,k in [B,H,S,D]; v TRANSPOSED [B,H,D,S]; att [B,S,INNER].
__device__ __half g_q[BB*HEADS*SS*DHEAD];
__device__ __half g_k[BB*HEADS*SS*DHEAD];
__device__ __half g_v[BB*HEADS*SS*DHEAD];
__device__ __half g_att[BB*SS*INNER];
__device__ __half g_rw[4*HID*INNER];   // Wq,Wk,Wv,Wo TRANSPOSED [n][k] fp16
__device__ __half g_rx[3*BB*SS*HID];   // query,key,value fp16

#define LOG2E 1.4426950408889634f

__device__ __forceinline__ __half hrn(float x) { return __float2half_rn(x); }

__device__ __forceinline__ uint32_t pack2(float a, float b) {
    __half2 h = __halves2half2(hrn(a), hrn(b));
    uint32_t u;
    *(__half2*)&u = h;
    return u;
}

__device__ __forceinline__ void mma16(float* c, const uint32_t* a, const uint32_t* b) {
    asm volatile(
        "mma.sync.aligned.m16n8k16.row.col.f32.f16.f16.f32 "
        "{%0,%1,%2,%3}, {%4,%5,%6,%7}, {%8,%9}, {%0,%1,%2,%3};"
        : "+f"(c[0]), "+f"(c[1]), "+f"(c[2]), "+f"(c[3])
        : "r"(a[0]), "r"(a[1]), "r"(a[2]), "r"(a[3]), "r"(b[0]), "r"(b[1]));
}

__device__ __forceinline__ void ldm4(uint32_t& r0, uint32_t& r1, uint32_t& r2,
                                     uint32_t& r3, uint32_t addr) {
    asm volatile(
        "ldmatrix.sync.aligned.m8n8.x4.shared.b16 {%0,%1,%2,%3}, [%4];"
        : "=r"(r0), "=r"(r1), "=r"(r2), "=r"(r3) : "r"(addr));
}

__device__ __forceinline__ uint32_t smaddr(const void* p) {
    return (uint32_t)__cvta_generic_to_shared(p);
}
__device__ __forceinline__ void cp16(uint32_t dst, const void* src) {
    asm volatile("cp.async.cg.shared.global [%0], [%1], 16;" :: "r"(dst), "l"(src));
}
__device__ __forceinline__ void cp_commit() {
    asm volatile("cp.async.commit_group;");
}
template <int N>
__device__ __forceinline__ void cp_wait() {
    asm volatile("cp.async.wait_group %0;" :: "n"(N));
}

// ---------------------------------------------------------------------------
// Unified pre-pass: z<3 -> fp32->fp16 convert of q/k/v; z>=3 -> weight
// transpose+convert. grid (32,32,7), 256 threads.
// ---------------------------------------------------------------------------
__global__ void prepass_kernel(const float* __restrict__ q,
                               const float* __restrict__ k,
                               const float* __restrict__ v,
                               const float* __restrict__ Wq,
                               const float* __restrict__ Wk,
                               const float* __restrict__ Wv,
                               const float* __restrict__ Wo,
                               __half* __restrict__ rx,
                               __half* __restrict__ rw) {
    const int z = blockIdx.z;
    const int tid = threadIdx.x;
    if (z < 3) {
        const float* src = (z == 0) ? q : (z == 1) ? k : v;
        const float4* __restrict__ s4 = (const float4*)src;
        uint2* __restrict__ d4 = (uint2*)(rx + (size_t)z * BB * SS * HID);
        const int blk = blockIdx.y * 32 + blockIdx.x;   // 0..1023
#pragma unroll
        for (int i = 0; i < 4; i++) {
            int idx = blk * 1024 + i * 256 + tid;       // 1M float4 total
            float4 vv = s4[idx];
            uint2 o;
            o.x = pack2(vv.x, vv.y);
            o.y = pack2(vv.z, vv.w);
            d4[idx] = o;
        }
    } else {
        __shared__ float t[32][33];
        const int zz = z - 3;
        const float* W = (zz == 0) ? Wq : (zz == 1) ? Wk : (zz == 2) ? Wv : Wo;
        __half* Wt = rw + (size_t)zz * HID * INNER;
        const int x0 = blockIdx.x * 32, y0 = blockIdx.y * 32;
        const int tx = tid & 31, ty = tid >> 5;         // ty 0..7
#pragma unroll
        for (int i = 0; i < 4; i++)
            t[ty + i * 8][tx] = W[(size_t)(y0 + ty + i * 8) * INNER + x0 + tx];
        __syncthreads();
#pragma unroll
        for (int i = 0; i < 4; i++)
            Wt[(size_t)(x0 + ty + i * 8) * HID + y0 + tx] = hrn(t[tx][ty + i * 8]);
    }
}

// ---------------------------------------------------------------------------
// fp16 GEMM, K-step 64 (16 barrier rounds), cp.async double-buffered.
// MODE: 0 = fp32 out row-major, 1 = fp16 scatter [B,H,S,D],
// 2 = fp16 scatter transposed [B,H,D,S].
// ---------------------------------------------------------------------------
#define GHS 72                        // halves per smem row (64 + 8 pad)
#define GT (128*GHS)                  // halves per tile buffer = 9216
#define GEMM_SMEM (4*GT*2)            // 2 A + 2 B buffers = 73728 bytes

template <int MODE>
__device__ __forceinline__ void gemm_body(const __half* __restrict__ X,
                                          const __half* __restrict__ Wt,
                                          const float* __restrict__ bias,
                                          void* __restrict__ outv,
                                          int m0, int n0) {
    extern __shared__ __align__(16) char smc[];
    __half* As = (__half*)smc;
    __half* Bs = As + 2 * GT;

    const int tid  = threadIdx.x;
    const int lane = tid & 31;
    const int wid  = tid >> 5;
    const int wm   = (wid >> 2) * 64;
    const int wn   = (wid & 3) * 32;

    const int cr = tid >> 3, cch = tid & 7;     // 32 rows/pass x 8 chunks
    const uint32_t asm0 = smaddr(As);
    const uint32_t bsm0 = smaddr(Bs);

    float c[4][4][4] = {};

#pragma unroll
    for (int i = 0; i < 4; i++) {
        int r = cr + i * 32;
        cp16(asm0 + (r * GHS + cch * 8) * 2, X + (size_t)(m0 + r) * HID + cch * 8);
        cp16(bsm0 + (r * GHS + cch * 8) * 2, Wt + (size_t)(n0 + r) * HID + cch * 8);
    }
    cp_commit();

    const int NT = HID / 64;
    for (int t = 0; t < NT; t++) {
        const int kt = t * 64;
        const int cur = t & 1;
        if (t + 1 < NT) {
            const int nxt = (t + 1) & 1;
#pragma unroll
            for (int i = 0; i < 4; i++) {
                int r = cr + i * 32;
                cp16(asm0 + (nxt * GT + r * GHS + cch * 8) * 2,
                     X + (size_t)(m0 + r) * HID + kt + 64 + cch * 8);
                cp16(bsm0 + (nxt * GT + r * GHS + cch * 8) * 2,
                     Wt + (size_t)(n0 + r) * HID + kt + 64 + cch * 8);
            }
            cp_commit();
            cp_wait<1>();
        } else {
            cp_wait<0>();
        }
        __syncthreads();

        const uint32_t* A32 = (const uint32_t*)(As + cur * GT);
        const uint32_t* B32 = (const uint32_t*)(Bs + cur * GT);
#pragma unroll
        for (int kk = 0; kk < 4; kk++) {
            uint32_t af[4][4], bf[4][2];
            const int ko = kk * 8 + (lane & 3);
#pragma unroll
            for (int mf = 0; mf < 4; mf++) {
                int row = wm + mf * 16 + (lane >> 2);
                af[mf][0] = A32[row * 36 + ko];
                af[mf][1] = A32[(row + 8) * 36 + ko];
                af[mf][2] = A32[row * 36 + ko + 4];
                af[mf][3] = A32[(row + 8) * 36 + ko + 4];
            }
#pragma unroll
            for (int nf = 0; nf < 4; nf++) {
                int n = wn + nf * 8 + (lane >> 2);
                bf[nf][0] = B32[n * 36 + ko];
                bf[nf][1] = B32[n * 36 + ko + 4];
            }
#pragma unroll
            for (int mf = 0; mf < 4; mf++)
#pragma unroll
                for (int nf = 0; nf < 4; nf++)
                    mma16(c[mf][nf], af[mf], bf[nf]);
        }
        __syncthreads();
    }

#pragma unroll
    for (int mf = 0; mf < 4; mf++) {
#pragma unroll
        for (int nf = 0; nf < 4; nf++) {
            int row = m0 + wm + mf * 16 + (lane >> 2);
            int col = n0 + wn + nf * 8 + (lane & 3) * 2;
            float v00 = c[mf][nf][0] + bias[col];
            float v01 = c[mf][nf][1] + bias[col + 1];
            float v10 = c[mf][nf][2] + bias[col];
            float v11 = c[mf][nf][3] + bias[col + 1];
            if (MODE == 0) {
                float* out = (float*)outv;
                *(float2*)(out + (size_t)row * INNER + col) = make_float2(v00, v01);
                *(float2*)(out + (size_t)(row + 8) * INNER + col) = make_float2(v10, v11);
            } else {
                int b = row >> 11, s = row & 2047;
                int h = col >> 6, d = col & 63;
                __half* out = (__half*)outv;
                if (MODE == 1) {
                    *(uint32_t*)(out + (((size_t)(b * HEADS + h)) * SS + s) * DHEAD + d) =
                        pack2(v00, v01);
                    *(uint32_t*)(out + (((size_t)(b * HEADS + h)) * SS + s + 8) * DHEAD + d) =
                        pack2(v10, v11);
                } else {
                    __half* base = out + ((size_t)(b * HEADS + h)) * DHEAD * SS;
                    base[(size_t)d * SS + s]           = hrn(v00);
                    base[(size_t)(d + 1) * SS + s]     = hrn(v01);
                    base[(size_t)d * SS + s + 8]       = hrn(v10);
                    base[(size_t)(d + 1) * SS + s + 8] = hrn(v11);
                }
            }
        }
    }
}

__global__ void __launch_bounds__(256)
gemm_qkv(const __half* __restrict__ rx, const __half* __restrict__ rw,
         const float* __restrict__ bq, const float* __restrict__ bk,
         const float* __restrict__ bv,
         __half* __restrict__ oq, __half* __restrict__ ok, __half* __restrict__ ov) {
    const int z = blockIdx.z;
    const __half* X = rx + (size_t)z * BB * SS * HID;
    const __half* W = rw + (size_t)z * HID * INNER;
    const float* bs = (z == 0) ? bq : (z == 1) ? bk : bv;
    if (z == 2)
        gemm_body<2>(X, W, bs, ov, blockIdx.y * 128, blockIdx.x * 128);
    else
        gemm_body<1>(X, W, bs, (z == 0) ? oq : ok, blockIdx.y * 128, blockIdx.x * 128);
}

__global__ void __launch_bounds__(256)
gemm_out(const __half* __restrict__ A, const __half* __restrict__ Wt,
         const float* __restrict__ bias, float* __restrict__ out) {
    gemm_body<0>(A, Wt, bias, out, blockIdx.y * 128, blockIdx.x * 128);
}

// ---------------------------------------------------------------------------
// Warp-specialized flash attention (as R16) with grid.y = 2h + b so the two
// batches' same-h blocks co-schedule -> bias dedups in L2.
// ---------------------------------------------------------------------------
#define KVS 72
#define KVROW_B (KVS*2)
#define KVH_T (2 * 64 * KVS)
#define CB_T (64 * 68)
#define QHS 72
#define ATTN_SMEM (2*KVH_T*2 + 2*CB_T*2 + 64*QHS*2)   // 63488

__device__ __forceinline__ void stage_cb(__half* cbb, const float* bp,
                                         const float* mp, int rbase,
                                         int rr, int c4) {
#pragma unroll
    for (int g = 0; g < 2; g++) {
        float4 bv4[4], mv4[4];
#pragma unroll
        for (int i = 0; i < 4; i++) {
            int r = (g * 4 + i) * 2 + rr;
            bv4[i] = *(const float4*)&bp[(size_t)r * SS + c4];
            mv4[i] = *(const float4*)&mp[(size_t)r * SS + c4];
        }
#pragma unroll
        for (int i = 0; i < 4; i++) {
            int r = (g * 4 + i) * 2 + rr;
            uint2 cb;
            cb.x = pack2((bv4[i].x * 0.125f + mv4[i].x) * LOG2E,
                         (bv4[i].y * 0.125f + mv4[i].y) * LOG2E);
            cb.y = pack2((bv4[i].z * 0.125f + mv4[i].z) * LOG2E,
                         (bv4[i].w * 0.125f + mv4[i].w) * LOG2E);
            *(uint2*)&cbb[(rbase + r) * 68 + c4] = cb;
        }
    }
}

__global__ void __launch_bounds__(256, 2)
attn_fp16(const float* __restrict__ bias, const float* __restrict__ mask) {
    extern __shared__ __align__(16) char smc[];
    __half* KV  = (__half*)smc;
    __half* CBh = (__half*)(smc + 2 * KVH_T * 2);
    __half* Qs  = (__half*)(smc + 2 * KVH_T * 2 + 2 * CB_T * 2);

    const int tid  = threadIdx.x;
    const int lane = tid & 31;
    const int wid  = tid >> 5;
    const bool consumer = (wid < 4);
    // y = 2h + b: same-h pairs adjacent -> bias shared via L2.
    const int h = blockIdx.y >> 1;
    const int b = blockIdx.y & 1;
    const int bh = b * HEADS + h;
    const int q0 = blockIdx.x * 64;

    const __half* qp = g_q + (size_t)bh * SS * DHEAD;
    const __half* kp = g_k + (size_t)bh * SS * DHEAD;
    const __half* vtp = g_v + (size_t)bh * DHEAD * SS;

    const int NT = SS / 64;

    if (consumer) {
#pragma unroll
        for (int i = 0; i < 4; i++) {
            int idx = tid + i * 128;
            int r = idx >> 3, ch = idx & 7;
            *(uint4*)(Qs + r * QHS + ch * 8) =
                *(const uint4*)(qp + (size_t)(q0 + r) * DHEAD + ch * 8);
        }
    } else {
        const int ptid = tid - 128;
        const int cr = ptid >> 3, cch = ptid & 7;
        uint32_t kd = smaddr(KV);
        uint32_t vd = kd + 64 * KVROW_B;
#pragma unroll
        for (int i = 0; i < 4; i++) {
            int r = cr + i * 16;
            cp16(kd + r * KVROW_B + cch * 16, kp + (size_t)r * DHEAD + cch * 8);
            cp16(vd + r * KVROW_B + cch * 16, vtp + (size_t)r * SS + cch * 8);
        }
        cp_commit();
        const int rbase = (wid - 4) * 16;
        const int rr = lane >> 4, c4 = (lane & 15) * 4;
        stage_cb(CBh, bias + ((size_t)h * SS + q0 + rbase) * SS,
                 mask + ((size_t)b * SS + q0 + rbase) * SS, rbase, rr, c4);
        cp_wait<0>();
    }
    __syncthreads();

    uint32_t qf[4][4];
    float osum[4] = {0.f, 0.f, 0.f, 0.f};
    float o[8][4] = {};
    const int grow0 = q0 + (wid & 3) * 16 + (lane >> 2);
    const int lr = lane >> 2;
    const int jrow = lane & 7;
    const int jlo  = (lane >> 3) & 1;
    const int jhi  = (lane >> 4) & 1;
    const uint32_t scl2 = pack2(0.125f * LOG2E, 0.125f * LOG2E);
    const uint32_t ones2 = 0x3C003C00u;
    const uint32_t bones[2] = {ones2, ones2};

    if (consumer) {
        const uint32_t* Q32 = (const uint32_t*)Qs;
        int qrow = wid * 16 + (lane >> 2);
#pragma unroll
        for (int kk = 0; kk < 4; kk++) {
            int ko = kk * 8 + (lane & 3);
            qf[kk][0] = Q32[qrow * 36 + ko];
            qf[kk][1] = Q32[(qrow + 8) * 36 + ko];
            qf[kk][2] = Q32[qrow * 36 + ko + 4];
            qf[kk][3] = Q32[(qrow + 8) * 36 + ko + 4];
        }
    }

    for (int t = 0; t < NT; t++) {
        if (consumer) {
            const uint32_t ksb = smaddr(KV) + (t & 1) * KVH_T * 2;
            const uint32_t vsb = ksb + 64 * KVROW_B;
            const __half* Cw = CBh + (t & 1) * CB_T + wid * 16 * 68;

            float s[8][4] = {};
#pragma unroll
            for (int kk = 0; kk < 4; kk++) {
                uint32_t bf[8][2];
#pragma unroll
                for (int np = 0; np < 4; np++) {
                    uint32_t addr = ksb + (np * 16 + jhi * 8 + jrow) * KVROW_B
                                  + kk * 32 + jlo * 16;
                    ldm4(bf[2 * np][0], bf[2 * np][1],
                         bf[2 * np + 1][0], bf[2 * np + 1][1], addr);
                }
#pragma unroll
                for (int nf = 0; nf < 8; nf++)
                    mma16(s[nf], qf[kk], bf[nf]);
            }

            uint32_t pp[8][2];
#pragma unroll
            for (int nf = 0; nf < 8; nf++) {
                int col = nf * 8 + (lane & 3) * 2;
                uint32_t c0 = *(const uint32_t*)&Cw[lr * 68 + col];
                uint32_t c1 = *(const uint32_t*)&Cw[(lr + 8) * 68 + col];
                uint32_t sh0 = pack2(s[nf][0], s[nf][1]);
                uint32_t sh1 = pack2(s[nf][2], s[nf][3]);
                uint32_t x0, x1;
                asm("fma.rn.f16x2 %0, %1, %2, %3;"
                    : "=r"(x0) : "r"(sh0), "r"(scl2), "r"(c0));
                asm("fma.rn.f16x2 %0, %1, %2, %3;"
                    : "=r"(x1) : "r"(sh1), "r"(scl2), "r"(c1));
                asm("ex2.approx.f16x2 %0, %1;" : "=r"(pp[nf][0]) : "r"(x0));
                asm("ex2.approx.f16x2 %0, %1;" : "=r"(pp[nf][1]) : "r"(x1));
            }

#pragma unroll
            for (int kk = 0; kk < 4; kk++) {
                uint32_t vb[8][2];
#pragma unroll
                for (int dp = 0; dp < 4; dp++) {
                    uint32_t addr = vsb + (dp * 16 + jhi * 8 + jrow) * KVROW_B
                                  + kk * 32 + jlo * 16;
                    ldm4(vb[2 * dp][0], vb[2 * dp][1],
                         vb[2 * dp + 1][0], vb[2 * dp + 1][1], addr);
                }
                uint32_t pa[4] = {pp[2 * kk][0], pp[2 * kk][1],
                                  pp[2 * kk + 1][0], pp[2 * kk + 1][1]};
#pragma unroll
                for (int df = 0; df < 8; df++)
                    mma16(o[df], pa, vb[df]);
                mma16(osum, pa, bones);
            }
        } else if (t + 1 < NT) {
            const int kt1 = (t + 1) * 64;
            const int ptid = tid - 128;
            const int cr = ptid >> 3, cch = ptid & 7;
            uint32_t kd = smaddr(KV) + ((t + 1) & 1) * KVH_T * 2;
            uint32_t vd = kd + 64 * KVROW_B;
#pragma unroll
            for (int i = 0; i < 4; i++) {
                int r = cr + i * 16;
                cp16(kd + r * KVROW_B + cch * 16,
                     kp + (size_t)(kt1 + r) * DHEAD + cch * 8);
                cp16(vd + r * KVROW_B + cch * 16,
                     vtp + (size_t)r * SS + kt1 + cch * 8);
            }
            cp_commit();

            const int rbase = (wid - 4) * 16;
            const int rr = lane >> 4, c4 = (lane & 15) * 4;
            stage_cb(CBh + ((t + 1) & 1) * CB_T,
                     bias + ((size_t)h * SS + q0 + rbase) * SS + kt1,
                     mask + ((size_t)b * SS + q0 + rbase) * SS + kt1,
                     rbase, rr, c4);
            cp_wait<0>();
        }
        __syncthreads();
    }

    if (consumer) {
        float inv0 = 1.f / osum[0], inv1 = 1.f / osum[2];
#pragma unroll
        for (int df = 0; df < 8; df++) {
            int colg = h * 64 + df * 8 + (lane & 3) * 2;
            *(uint32_t*)(g_att + ((size_t)b * SS + grow0) * INNER + colg) =
                pack2(o[df][0] * inv0, o[df][1] * inv0);
            *(uint32_t*)(g_att + ((size_t)b * SS + grow0 + 8) * INNER + colg) =
                pack2(o[df][2] * inv1, o[df][3] * inv1);
        }
    }
}

// ---------------------------------------------------------------------------

extern "C" void kernel_launch(void* const* d_in, const int* in_sizes, int n_in,
                              void* d_out, int out_size) {
    const float* query = (const float*)d_in[0];
    const float* key_i = (const float*)d_in[1];
    const float* value = (const float*)d_in[2];
    const float* mask  = (const float*)d_in[3];
    const float* pbias = (const float*)d_in[4];
    const float* Wq = (const float*)d_in[5];
    const float* bq = (const float*)d_in[6];
    const float* Wk = (const float*)d_in[7];
    const float* bk = (const float*)d_in[8];
    const float* Wv = (const float*)d_in[9];
    const float* bv = (const float*)d_in[10];
    const float* Wo = (const float*)d_in[11];
    const float* bo = (const float*)d_in[12];
    float* out = (float*)d_out;

    __half *qb, *kb, *vb, *ab, *rw, *rx;
    cudaGetSymbolAddress((void**)&qb, g_q);
    cudaGetSymbolAddress((void**)&kb, g_k);
    cudaGetSymbolAddress((void**)&vb, g_v);
    cudaGetSymbolAddress((void**)&ab, g_att);
    cudaGetSymbolAddress((void**)&rw, g_rw);
    cudaGetSymbolAddress((void**)&rx, g_rx);

    dim3 grid_pre(32, 32, 7);
    prepass_kernel<<<grid_pre, 256>>>(query, key_i, value, Wq, Wk, Wv, Wo, rx, rw);

    cudaFuncSetAttribute(gemm_qkv, cudaFuncAttributeMaxDynamicSharedMemorySize, GEMM_SMEM);
    cudaFuncSetAttribute(gemm_out, cudaFuncAttributeMaxDynamicSharedMemorySize, GEMM_SMEM);
    dim3 grid_qkv(INNER / 128, (BB * SS) / 128, 3);
    gemm_qkv<<<grid_qkv, 256, GEMM_SMEM>>>(rx, rw, bq, bk, bv, qb, kb, vb);

    cudaFuncSetAttribute(attn_fp16, cudaFuncAttributeMaxDynamicSharedMemorySize, ATTN_SMEM);
    dim3 grid_attn(SS / 64, BH);     // y = 2h + b
    attn_fp16<<<grid_attn, 256, ATTN_SMEM>>>(pbias, mask);

    dim3 grid_gemm(INNER / 128, (BB * SS) / 128);
    gemm_out<<<grid_gemm, 256, GEMM_SMEM>>>(ab, rw + 3 * (size_t)HID * INNER, bo, out);
}